// round 1
// baseline (speedup 1.0000x reference)
#include <cuda_runtime.h>
#include <cstdint>

// Shapes (fixed per reference setup_inputs)
#define B_  16
#define H_  64
#define W_  64
#define C_  256
#define HO_ 128
#define WO_ 128
// per-batch output volume
#define OUT_PER_B (HO_ * WO_ * C_)          // 4,194,304
#define N_IN      (B_ * H_ * W_ * C_)       // 16,777,216
#define N_OUT     (B_ * OUT_PER_B)          // 67,108,864

__global__ void zero_out_kernel(float4* __restrict__ out, int n4) {
    int idx = blockIdx.x * blockDim.x + threadIdx.x;
    int stride = gridDim.x * blockDim.x;
    float4 z = make_float4(0.f, 0.f, 0.f, 0.f);
    for (int i = idx; i < n4; i += stride) {
        out[i] = z;
    }
}

__global__ void scatter_add_kernel(const float4* __restrict__ updates4,
                                   const int4* __restrict__ mask4,
                                   float* __restrict__ out) {
    int i = blockIdx.x * blockDim.x + threadIdx.x;   // index into groups of 4
    const int n4 = N_IN / 4;
    if (i >= n4) return;

    // flat element index of first lane of this group
    int e0 = i * 4;
    // which batch and which channel (channels are contiguous innermost, C=256 divisible by 4)
    int b = e0 / (H_ * W_ * C_);
    int c0 = e0 & (C_ - 1);                 // channel of element 0 (c0..c0+3 consecutive)
    long long out_b_base = (long long)b * OUT_PER_B;

    int4  m = mask4[i];
    float4 u = updates4[i];

    // decode: y = m / (WO_*C_); x = (m / C_) % WO_; offset = ((y*WO_)+x)*C_ + c
    // note: ((m / (WO_*C_)) * WO_ + (m / C_) % WO_) * C_ == (m / C_) * C_  ... careful:
    //   m/C_ = y*WO_ + x  exactly (since m < HO_*WO_*C_). So spatial offset = (m / C_) * C_.
    {
        int sp = (m.x / C_) * C_;
        atomicAdd(out + out_b_base + sp + (c0 + 0), u.x);
    }
    {
        int sp = (m.y / C_) * C_;
        atomicAdd(out + out_b_base + sp + (c0 + 1), u.y);
    }
    {
        int sp = (m.z / C_) * C_;
        atomicAdd(out + out_b_base + sp + (c0 + 2), u.z);
    }
    {
        int sp = (m.w / C_) * C_;
        atomicAdd(out + out_b_base + sp + (c0 + 3), u.w);
    }
}

extern "C" void kernel_launch(void* const* d_in, const int* in_sizes, int n_in,
                              void* d_out, int out_size) {
    const float4* updates4 = (const float4*)d_in[0];
    const int4*   mask4    = (const int4*)d_in[1];
    float*        out      = (float*)d_out;

    // 1) zero the output (268 MB)
    {
        int n4 = N_OUT / 4;                 // 16,777,216 float4 stores
        int threads = 256;
        int blocks = 148 * 8;               // grid-stride, ~full chip
        zero_out_kernel<<<blocks, threads>>>((float4*)out, n4);
    }

    // 2) scatter-add
    {
        int n4 = N_IN / 4;                  // 4,194,304 groups
        int threads = 256;
        int blocks = (n4 + threads - 1) / threads;
        scatter_add_kernel<<<blocks, threads>>>(updates4, mask4, out);
    }
}

// round 2
// speedup vs baseline: 1.1190x; 1.1190x over previous
#include <cuda_runtime.h>
#include <cstdint>

// Shapes (fixed per reference setup_inputs)
#define B_  16
#define H_  64
#define W_  64
#define C_  256                      // power of two
#define HO_ 128
#define WO_ 128
#define OUT_PER_B (HO_ * WO_ * C_)   // 4,194,304 = 2^22
#define IN_PER_B  (H_ * W_ * C_)     // 1,048,576 = 2^20
#define N_IN      (B_ * IN_PER_B)    // 16,777,216
#define N_OUT     (B_ * OUT_PER_B)   // 67,108,864

// Chunking: 2 batches per chunk -> 33.5 MB output region (L2 is ~126 MB).
#define CHUNK_B       2
#define NCHUNK        (B_ / CHUNK_B)                  // 8
#define CHUNK_OUT_F   (CHUNK_B * OUT_PER_B)           // 8,388,608 floats
#define CHUNK_OUT_F4  (CHUNK_OUT_F / 4)               // 2,097,152 float4
#define CHUNK_IN_E    (CHUNK_B * IN_PER_B)            // 2,097,152 elements
#define CHUNK_GROUPS  (CHUNK_IN_E / 4)                // 524,288 groups of 4

#define ZERO_BLOCKS   512
#define SCAT_BLOCKS   (CHUNK_GROUPS / 256)            // 2048
#define THREADS       256

// Zero one chunk's output region (used to prime chunk 0).
__global__ void zero_chunk0_kernel(float4* __restrict__ out4) {
    float4 z = make_float4(0.f, 0.f, 0.f, 0.f);
    int stride = gridDim.x * blockDim.x;
    for (int i = blockIdx.x * blockDim.x + threadIdx.x; i < CHUNK_OUT_F4; i += stride)
        out4[i] = z;
}

// Fused: blocks [0, ZERO_BLOCKS) zero chunk+1's region (keeping it L2-resident
// for the NEXT kernel); blocks [ZERO_BLOCKS, ...) scatter chunk's elements into
// the region zeroed by the PREVIOUS kernel (still L2-resident -> atomics hit L2).
__global__ void fused_scatter_kernel(const float4* __restrict__ updates4,
                                     const int4*   __restrict__ mask4,
                                     float*        __restrict__ out,
                                     int chunk) {
    if (blockIdx.x < ZERO_BLOCKS) {
        // zero next chunk's region
        if (chunk + 1 < NCHUNK) {
            float4* dst = (float4*)(out + (size_t)(chunk + 1) * CHUNK_OUT_F);
            float4 z = make_float4(0.f, 0.f, 0.f, 0.f);
            int stride = ZERO_BLOCKS * blockDim.x;
            for (int i = blockIdx.x * blockDim.x + threadIdx.x; i < CHUNK_OUT_F4; i += stride)
                dst[i] = z;
        }
        return;
    }

    int i = (blockIdx.x - ZERO_BLOCKS) * blockDim.x + threadIdx.x;  // group within chunk
    if (i >= CHUNK_GROUPS) return;
    int g  = chunk * CHUNK_GROUPS + i;     // global group index
    int e0 = g << 2;                       // first element index of the group
    int b  = e0 >> 20;                     // / IN_PER_B
    int c0 = e0 & (C_ - 1);                // channel of element 0 (c0..c0+3)
    size_t out_b_base = (size_t)b << 22;   // * OUT_PER_B

    int4   m = mask4[g];
    float4 u = updates4[g];

    // spatial byte offset: (mask / C) * C == mask & ~(C-1)
    float* ob = out + out_b_base;
    atomicAdd(ob + (m.x & ~(C_ - 1)) + c0 + 0, u.x);
    atomicAdd(ob + (m.y & ~(C_ - 1)) + c0 + 1, u.y);
    atomicAdd(ob + (m.z & ~(C_ - 1)) + c0 + 2, u.z);
    atomicAdd(ob + (m.w & ~(C_ - 1)) + c0 + 3, u.w);
}

extern "C" void kernel_launch(void* const* d_in, const int* in_sizes, int n_in,
                              void* d_out, int out_size) {
    const float4* updates4 = (const float4*)d_in[0];
    const int4*   mask4    = (const int4*)d_in[1];
    float*        out      = (float*)d_out;

    // Prime: zero chunk 0's region (small, L2-resident when chunk 0 scatters)
    zero_chunk0_kernel<<<ZERO_BLOCKS, THREADS>>>((float4*)out);

    // Pipelined chunks: scatter chunk c while zeroing chunk c+1
    for (int c = 0; c < NCHUNK; c++) {
        fused_scatter_kernel<<<ZERO_BLOCKS + SCAT_BLOCKS, THREADS>>>(
            updates4, mask4, out, c);
    }
}

// round 3
// speedup vs baseline: 1.1462x; 1.0243x over previous
#include <cuda_runtime.h>
#include <cstdint>

// Shapes (fixed per reference setup_inputs)
#define B_  16
#define H_  64
#define W_  64
#define C_  256
#define HO_ 128
#define WO_ 128
#define OUT_PER_B (HO_ * WO_ * C_)   // 4,194,304 = 2^22
#define IN_PER_B  (H_ * W_ * C_)     // 1,048,576 = 2^20
#define N_IN      (B_ * IN_PER_B)    // 16,777,216
#define N_OUT     (B_ * OUT_PER_B)   // 67,108,864

// 2 batches per chunk -> 33.5 MB destination region; current + next = 67 MB < L2 (126 MB)
#define CHUNK_B       2
#define NCHUNK        (B_ / CHUNK_B)                  // 8
#define CHUNK_OUT_F   (CHUNK_B * OUT_PER_B)           // 8,388,608 floats
#define CHUNK_OUT_F4  (CHUNK_OUT_F / 4)               // 2,097,152 float4
#define CHUNK_GROUPS  ((CHUNK_B * IN_PER_B) / 4)      // 524,288 groups of 4 elems

#define BLOCKS   1024
#define THREADS  256
#define NTHREADS (BLOCKS * THREADS)                   // 262,144
#define ZERO_ITERS (CHUNK_OUT_F4 / NTHREADS)          // 8
#define GRP_ITERS  (CHUNK_GROUPS / NTHREADS)          // 2

__global__ void zero_chunk0_kernel(float4* __restrict__ out4) {
    int tid = blockIdx.x * blockDim.x + threadIdx.x;
    float4 z = make_float4(0.f, 0.f, 0.f, 0.f);
#pragma unroll
    for (int j = 0; j < ZERO_ITERS; j++)
        out4[tid + j * NTHREADS] = z;
}

// Every block: (a) zero its slice of chunk+1's region (kept L2-resident for the
// NEXT kernel), (b) scatter its slice of this chunk's inputs into the region
// zeroed by the PREVIOUS kernel (L2-resident -> atomics resolve in L2).
__global__ void __launch_bounds__(THREADS) fused_scatter_kernel(
        const float4* __restrict__ updates4,
        const int4*   __restrict__ mask4,
        float*        __restrict__ out,
        int chunk) {
    int tid = blockIdx.x * blockDim.x + threadIdx.x;   // 0 .. NTHREADS-1

    // ---- (a) zero a slice of next chunk's destination ----
    if (chunk + 1 < NCHUNK) {
        float4* dst = (float4*)(out + (size_t)(chunk + 1) * CHUNK_OUT_F);
        float4 z = make_float4(0.f, 0.f, 0.f, 0.f);
#pragma unroll
        for (int j = 0; j < ZERO_ITERS; j++)
            dst[tid + j * NTHREADS] = z;
    }

    // ---- (b) scatter 2 groups (8 elements, 8 atomics) ----
    int g0 = chunk * CHUNK_GROUPS + tid;
    int g1 = g0 + NTHREADS;

    int4   ma = mask4[g0];
    float4 ua = updates4[g0];
    int4   mb = mask4[g1];
    float4 ub = updates4[g1];

    // group g covers elements e0..e0+3; b = e0/IN_PER_B, c0 = e0 % C
    int e0a = g0 << 2;
    int e0b = g1 << 2;
    float* oa = out + ((size_t)(e0a >> 20) << 22) + (e0a & (C_ - 1));
    float* ob = out + ((size_t)(e0b >> 20) << 22) + (e0b & (C_ - 1));

    // spatial offset: (mask / C) * C == mask & ~(C-1); channel added via base ptr
    atomicAdd(oa + (ma.x & ~(C_ - 1)) + 0, ua.x);
    atomicAdd(oa + (ma.y & ~(C_ - 1)) + 1, ua.y);
    atomicAdd(oa + (ma.z & ~(C_ - 1)) + 2, ua.z);
    atomicAdd(oa + (ma.w & ~(C_ - 1)) + 3, ua.w);
    atomicAdd(ob + (mb.x & ~(C_ - 1)) + 0, ub.x);
    atomicAdd(ob + (mb.y & ~(C_ - 1)) + 1, ub.y);
    atomicAdd(ob + (mb.z & ~(C_ - 1)) + 2, ub.z);
    atomicAdd(ob + (mb.w & ~(C_ - 1)) + 3, ub.w);
}

extern "C" void kernel_launch(void* const* d_in, const int* in_sizes, int n_in,
                              void* d_out, int out_size) {
    const float4* updates4 = (const float4*)d_in[0];
    const int4*   mask4    = (const int4*)d_in[1];
    float*        out      = (float*)d_out;

    // Prime: zero chunk 0's region (stays L2-resident for the first scatter)
    zero_chunk0_kernel<<<BLOCKS, THREADS>>>((float4*)out);

    // Pipelined chunks: scatter chunk c while zeroing chunk c+1
    for (int c = 0; c < NCHUNK; c++) {
        fused_scatter_kernel<<<BLOCKS, THREADS>>>(updates4, mask4, out, c);
    }
}

// round 4
// speedup vs baseline: 1.2396x; 1.0815x over previous
#include <cuda_runtime.h>
#include <cstdint>

// Shapes (fixed per reference setup_inputs)
#define B_  16
#define C_  256
#define OUT_PER_B (128 * 128 * 256)      // 4,194,304 = 2^22
#define IN_PER_B  (64 * 64 * 256)        // 1,048,576 = 2^20

// 2 batches per chunk; zero of chunk c+1 overlaps scatter of chunk c.
#define CHUNK_B          2
#define NCHUNK           8
#define CHUNK_OUT_F      (CHUNK_B * OUT_PER_B)       // 8,388,608 floats
#define CHUNK_OUT_BYTES  (CHUNK_OUT_F * 4)           // 33,554,432 B
#define CHUNK_GROUPS     ((CHUNK_B * IN_PER_B) / 4)  // 524,288 groups of 4

#define BLOCKS   1184                    // 148 SMs * 8 CTAs
#define THREADS  256
#define NTHREADS (BLOCKS * THREADS)      // 303,104

// TMA zero tiles
#define ZTILE_BYTES       16384
#define ZTILES_PER_CHUNK  (CHUNK_OUT_BYTES / ZTILE_BYTES)   // 2048

__device__ __forceinline__ uint32_t smem_u32(const void* p) {
    uint32_t a;
    asm("{ .reg .u64 t; cvta.to.shared.u64 t, %1; cvt.u32.u64 %0, t; }"
        : "=r"(a) : "l"(p));
    return a;
}

// Zero `region` [CHUNK_OUT_BYTES] via TMA bulk stores from a zeroed smem tile.
__device__ __forceinline__ void tma_zero_region(char* region, float4* zbuf) {
    // cooperatively zero the smem tile: 16384 B / 256 thr = 64 B = 4 float4
    float4 z = make_float4(0.f, 0.f, 0.f, 0.f);
#pragma unroll
    for (int j = 0; j < 4; j++)
        zbuf[threadIdx.x + j * THREADS] = z;
    __syncthreads();

    if (threadIdx.x == 0) {
        asm volatile("fence.proxy.async.shared::cta;" ::: "memory");
        uint32_t src = smem_u32(zbuf);
        for (int t = blockIdx.x; t < ZTILES_PER_CHUNK; t += BLOCKS) {
            char* dst = region + (size_t)t * ZTILE_BYTES;
            asm volatile(
                "cp.async.bulk.global.shared::cta.bulk_group [%0], [%1], %2;"
                :: "l"(dst), "r"(src), "n"(ZTILE_BYTES) : "memory");
        }
        asm volatile("cp.async.bulk.commit_group;" ::: "memory");
        asm volatile("cp.async.bulk.wait_group 0;" ::: "memory");
    }
}

__global__ void __launch_bounds__(THREADS) zero_chunk0_kernel(float* __restrict__ out) {
    __shared__ __align__(128) float4 zbuf[ZTILE_BYTES / 16];
    tma_zero_region((char*)out, zbuf);
}

// Kernel for chunk c: scatter chunk c's inputs (region zeroed by previous
// kernel) while TMA-zeroing chunk c+1's region for the next kernel.
__global__ void __launch_bounds__(THREADS) fused_scatter_kernel(
        const float4* __restrict__ updates4,
        const int4*   __restrict__ mask4,
        float*        __restrict__ out,
        int chunk) {
    __shared__ __align__(128) float4 zbuf[ZTILE_BYTES / 16];

    int tid = blockIdx.x * blockDim.x + threadIdx.x;

    // ---- prefetch this chunk's scatter inputs (hide latency under zeroing) ----
    int g0 = chunk * CHUNK_GROUPS + tid;                 // always valid
    int g1 = g0 + NTHREADS;
    bool has1 = (tid + NTHREADS) < CHUNK_GROUPS;

    int4   ma = mask4[g0];
    float4 ua = updates4[g0];
    int4   mb;
    float4 ub;
    if (has1) { mb = mask4[g1]; ub = updates4[g1]; }

    // ---- TMA-zero next chunk's destination region ----
    if (chunk + 1 < NCHUNK) {
        char* region = (char*)(out + (size_t)(chunk + 1) * CHUNK_OUT_F);
        tma_zero_region(region, zbuf);
    }

    // ---- scatter: pure RED.ADD stream on the LSU ----
    // dest = out + b*OUT_PER_B + (mask & ~(C-1)) + channel; channel folded into base
    int e0a = g0 << 2;
    float* oa = out + ((size_t)(e0a >> 20) << 22) + (e0a & (C_ - 1));
    atomicAdd(oa + (ma.x & ~(C_ - 1)) + 0, ua.x);
    atomicAdd(oa + (ma.y & ~(C_ - 1)) + 1, ua.y);
    atomicAdd(oa + (ma.z & ~(C_ - 1)) + 2, ua.z);
    atomicAdd(oa + (ma.w & ~(C_ - 1)) + 3, ua.w);

    if (has1) {
        int e0b = g1 << 2;
        float* ob = out + ((size_t)(e0b >> 20) << 22) + (e0b & (C_ - 1));
        atomicAdd(ob + (mb.x & ~(C_ - 1)) + 0, ub.x);
        atomicAdd(ob + (mb.y & ~(C_ - 1)) + 1, ub.y);
        atomicAdd(ob + (mb.z & ~(C_ - 1)) + 2, ub.z);
        atomicAdd(ob + (mb.w & ~(C_ - 1)) + 3, ub.w);
    }
}

extern "C" void kernel_launch(void* const* d_in, const int* in_sizes, int n_in,
                              void* d_out, int out_size) {
    const float4* updates4 = (const float4*)d_in[0];
    const int4*   mask4    = (const int4*)d_in[1];
    float*        out      = (float*)d_out;

    // Prime: zero chunk 0's region via TMA
    zero_chunk0_kernel<<<BLOCKS, THREADS>>>(out);

    // Pipelined chunks: scatter chunk c while zeroing chunk c+1
    for (int c = 0; c < NCHUNK; c++) {
        fused_scatter_kernel<<<BLOCKS, THREADS>>>(updates4, mask4, out, c);
    }
}